// round 11
// baseline (speedup 1.0000x reference)
#include <cuda_runtime.h>
#include <cuda_bf16.h>
#include <cstdint>

// SINDy_SHRED via fragment-direct HMMA, zero theta staging.
// R11 == R10 resubmit (R10 bench was an infra failure: container broke twice).
//
// dz[16 dims, 8 samples] = C^T[16, 192] @ Theta^T[192, 8] per warp-step.
//  - A = permuted masked C^T: static fragments (48 regs), built once.
//  - B = Theta^T generated DIRECTLY in fragment registers. k-rows are
//    c4-dependent; divergence avoided by permuting features so thread c4's
//    slots are a rotation (by 4*c4) of one fixed slot template, and storing
//    z rotated: zrot[t] = z[(t+4*c4)&15]. All indices compile-time.
//  - quad features via circulant classes {a, a+delta}: slots
//    zrot[m]*zrot[m+delta], m=0..3 cover all 16 rotations once per delta
//    (delta=8 twice; duplicates get zero C rows). C permutation done at init.
//  - dz redistributed through a 640B/warp smem tile, read rotated.
// R9 profile: L1=89.5% from the 22.5KB/warp-step theta SMEM round trip;
// this design moves ~1.3KB/warp-step instead.

#define LATENT 16
#define NFEAT 169
#define NSTEPS 10
#define DT_F 0.01f
#define KC 12                // k-steps of 16 -> 192 slots (169 features + pad)
#define KROWS 192
#define WARPS 8
#define BLOCK 256
#define SCTA 64              // samples per CTA = 8 warps * 8
#define CT_STRIDE 192        // CpermT row length in bf16 (per dim)
#define DZS 20               // dz tile row stride in f32 words (80B)

__host__ __device__ __forceinline__ constexpr int quad_row(int i, int j) {
    return 17 + 16 * i - (i * (i - 1)) / 2 + (j - i);
}

// ---------- helpers ----------
__device__ __forceinline__ uint32_t smem_u32(const void* p) {
    return (uint32_t)__cvta_generic_to_shared(p);
}
__device__ __forceinline__ uint32_t cvt_bf16x2(float hi, float lo) {
    uint32_t r;
    asm("cvt.rn.bf16x2.f32 %0, %1, %2;" : "=r"(r) : "f"(hi), "f"(lo));
    return r;
}
__device__ __forceinline__ void mma16816(float* d, const uint32_t* a, const uint32_t* b) {
    asm volatile(
        "mma.sync.aligned.m16n8k16.row.col.f32.bf16.bf16.f32 "
        "{%0,%1,%2,%3}, {%4,%5,%6,%7}, {%8,%9}, {%0,%1,%2,%3};"
        : "+f"(d[0]), "+f"(d[1]), "+f"(d[2]), "+f"(d[3])
        : "r"(a[0]), "r"(a[1]), "r"(a[2]), "r"(a[3]), "r"(b[0]), "r"(b[1]));
}

// ---------- slot template (uniform across threads; indices compile-time) ----
// s: 0 CONST | 1..4 LIN m=s-1 | 5..8 SQ m=s-5 | 9..36 DPROD d=1+(s-9)/4,m=(s-9)%4
//    | 37..40 D8 m=s-37 | 41..44 SIN m=s-41 | 45..47 ZERO
template <int S>
__device__ __forceinline__ float slot_val(const float* zr) {
    if constexpr (S == 0) return 1.0f;
    else if constexpr (S <= 4) return zr[S - 1];
    else if constexpr (S <= 8) { constexpr int m = S - 5; return zr[m] * zr[m]; }
    else if constexpr (S <= 36) {
        constexpr int d = 1 + (S - 9) / 4, m = (S - 9) % 4;
        return zr[m] * zr[(m + d) & 15];
    }
    else if constexpr (S <= 40) { constexpr int m = S - 37; return zr[m] * zr[m + 8]; }
    else if constexpr (S <= 44) return __sinf(zr[S - 41]);
    else return 0.0f;
}

// real feature index for slot s as seen by thread c4 (for the C permutation)
__device__ __forceinline__ int slot_feature(int s, int c4) {
    if (s == 0) return (c4 == 0) ? 0 : -1;
    if (s <= 4)  { int a = (s - 1 + 4 * c4) & 15; return 1 + a; }
    if (s <= 8)  { int a = (s - 5 + 4 * c4) & 15; return quad_row(a, a); }
    if (s <= 36) {
        int d = 1 + (s - 9) / 4, m = (s - 9) % 4;
        int a = (m + 4 * c4) & 15, b = (a + d) & 15;
        int i = a < b ? a : b, j = a < b ? b : a;
        return quad_row(i, j);
    }
    if (s <= 40) { int a = (s - 37 + 4 * c4) & 15; return (a < 8) ? quad_row(a, a + 8) : -1; }
    if (s <= 44) { int a = (s - 41 + 4 * c4) & 15; return 153 + a; }
    return -1;
}

// build B fragments and run the 12 chained MMAs (even/odd accumulators)
template <int K>
__device__ __forceinline__ void do_ksteps(const float* zr, const uint32_t (&A)[KC][4],
                                          float (&De)[4], float (&Do)[4]) {
    if constexpr (K < KC) {
        uint32_t b[2];
        b[0] = cvt_bf16x2(slot_val<K * 4 + 1>(zr), slot_val<K * 4 + 0>(zr));
        b[1] = cvt_bf16x2(slot_val<K * 4 + 3>(zr), slot_val<K * 4 + 2>(zr));
        mma16816((K & 1) ? Do : De, A[K], b);
        do_ksteps<K + 1>(zr, A, De, Do);
    }
}

// ---------- kernel ----------
__global__ __launch_bounds__(BLOCK, 2) void sindy_shred_fd_kernel(
    const float* __restrict__ h_t,
    const float* __restrict__ coef,
    const float* __restrict__ mask,
    float* __restrict__ out,
    int n, int nrep)
{
    // Permuted masked coefficients, transposed: sCT[d][kr] (bf16)
    __shared__ __align__(16) __nv_bfloat16 sCT[LATENT * CT_STRIDE];
    // per-warp dz tile: 8 sample-rows x 20 f32 words (80B, conflict-tuned)
    __shared__ __align__(16) float sdz[WARPS * 8 * DZS];

    const int tid  = threadIdx.x;
    const int lane = tid & 31;
    const int warp = tid >> 5;
    const int c4   = lane & 3;
    const int g    = lane >> 2;
    const int r    = blockIdx.y;

    // ---- init: build permuted C^T in smem ----
    {
        const float* cb = coef + (size_t)r * NFEAT * LATENT;
        const float* mb = mask + (size_t)r * NFEAT * LATENT;
        for (int idx = tid; idx < KROWS * LATENT; idx += BLOCK) {
            int kr = idx >> 4, d = idx & 15;
            int c4k = (kr >> 1) & 3;
            int p   = (kr & 1) | (((kr >> 3) & 1) << 1);
            int s   = (kr >> 4) * 4 + p;
            int f   = slot_feature(s, c4k);
            float v = 0.0f;
            if (f >= 0) v = cb[f * LATENT + d] * mb[f * LATENT + d];
            sCT[d * CT_STRIDE + kr] = __float2bfloat16(v);
        }
    }
    __syncthreads();

    // ---- static A fragments: A[k][0..3] per kstep ----
    // a0=(dim g, k 2c4,2c4+1) a1=(g+8, same) a2=(g, +8) a3=(g+8, +8)
    uint32_t A[KC][4];
    {
        const uint32_t* ctp = reinterpret_cast<const uint32_t*>(sCT);
        #pragma unroll
        for (int k = 0; k < KC; k++) {
            const int ku = 8 * k + c4;  // u32 index of (k*16 + 2c4)/2
            A[k][0] = ctp[g * (CT_STRIDE / 2) + ku];
            A[k][1] = ctp[(g + 8) * (CT_STRIDE / 2) + ku];
            A[k][2] = ctp[g * (CT_STRIDE / 2) + ku + 4];
            A[k][3] = ctp[(g + 8) * (CT_STRIDE / 2) + ku + 4];
        }
    }

    // ---- rotated z load: zr[t] = z[(t+4c4)&15] ----
    const int sample = blockIdx.x * SCTA + warp * 8 + g;
    const bool valid = sample < n;
    float zr[LATENT];
    #pragma unroll
    for (int d = 0; d < LATENT; d++) zr[d] = 0.0f;
    if (valid) {
        const float4* hp = reinterpret_cast<const float4*>(h_t + (size_t)sample * LATENT);
        #pragma unroll
        for (int q = 0; q < 4; q++) {
            float4 v = hp[(q + c4) & 3];
            zr[4*q+0] = v.x; zr[4*q+1] = v.y; zr[4*q+2] = v.z; zr[4*q+3] = v.w;
        }
    }

    float* dzw = sdz + warp * 8 * DZS;

    #pragma unroll 1
    for (int st = 0; st < NSTEPS; st++) {
        float De[4] = {0.f, 0.f, 0.f, 0.f};
        float Do[4] = {0.f, 0.f, 0.f, 0.f};
        do_ksteps<0>(zr, A, De, Do);

        // scatter dz (real-dim indexed): D frag: d0=(dim g, samp 2c4),
        // d1=(g, 2c4+1), d2=(g+8, 2c4), d3=(g+8, 2c4+1). Layout [samp][dim].
        dzw[(2*c4)     * DZS + g    ] = De[0] + Do[0];
        dzw[(2*c4 + 1) * DZS + g    ] = De[1] + Do[1];
        dzw[(2*c4)     * DZS + g + 8] = De[2] + Do[2];
        dzw[(2*c4 + 1) * DZS + g + 8] = De[3] + Do[3];
        __syncwarp();

        // gather own sample's dz, rotated: zrot block q = real block (q+c4)&3
        #pragma unroll
        for (int q = 0; q < 4; q++) {
            const int blk = (q + c4) & 3;
            float4 dv = *reinterpret_cast<const float4*>(dzw + g * DZS + blk * 4);
            zr[4*q+0] = fmaf(dv.x, DT_F, zr[4*q+0]);
            zr[4*q+1] = fmaf(dv.y, DT_F, zr[4*q+1]);
            zr[4*q+2] = fmaf(dv.z, DT_F, zr[4*q+2]);
            zr[4*q+3] = fmaf(dv.w, DT_F, zr[4*q+3]);
        }
        __syncwarp();   // reads done before next step's scatter
    }

    // ---- output: thread c4 writes real-dim block c4 = zrot block 0 ----
    if (valid) {
        float4 v;
        v.x = zr[0]; v.y = zr[1]; v.z = zr[2]; v.w = zr[3];
        reinterpret_cast<float4*>(out + ((size_t)sample * nrep + r) * LATENT)[c4] = v;
    }
}

extern "C" void kernel_launch(void* const* d_in, const int* in_sizes, int n_in,
                              void* d_out, int out_size) {
    const float* h_t  = (const float*)d_in[0];
    const float* coef = (const float*)d_in[1];
    const float* mask = (const float*)d_in[2];
    float* out = (float*)d_out;

    int n    = in_sizes[0] / LATENT;            // samples
    int nrep = in_sizes[1] / (NFEAT * LATENT);  // replicates

    dim3 block(BLOCK);
    dim3 grid((n + SCTA - 1) / SCTA, nrep);
    sindy_shred_fd_kernel<<<grid, block>>>(h_t, coef, mask, out, n, nrep);
}

// round 12
// speedup vs baseline: 1.4604x; 1.4604x over previous
#include <cuda_runtime.h>
#include <cuda_bf16.h>
#include <cstdint>

// SINDy_SHRED, fragment-direct HMMA v2: A-side theta generation.
// dz[16 samples, 16 dims] = Theta[16, 192] @ C_perm[192, 16] per warp-step.
//  - A = Theta fragments built DIRECTLY in registers: thread (g,c4) owns rows
//    (samples) g,g+8 and k-cols 2c4,2c4+1,+8,+9 -- same k-ownership as R11's
//    B operand, so the validated slot template + C permutation carry over;
//    thread evaluates the template on TWO rotated z vectors (samples g, g+8).
//  - B = permuted masked C^T: 48 static regs (R11's extraction, validated).
//  - dz exchange via XOR-block-swizzled smem tile: conflict-free STS.64
//    scatter and rotated LDS.128 gather (R11's DZS=20 tile had 2-4 way
//    conflicts; its L1=74.6% was the regression).
// 16 samples/warp-step (vs R11's 8) halves per-sample fixed overhead.

#define LATENT 16
#define NFEAT 169
#define NSTEPS 10
#define DT_F 0.01f
#define KC 12                // k-steps of 16 -> 192 slots
#define KROWS 192
#define WARPS 8
#define BLOCK 256
#define SPW 16               // samples per warp
#define SCTA (WARPS * SPW)   // 128
#define CT_STRIDE 192        // permuted C^T row length in bf16 (per dim)

__host__ __device__ __forceinline__ constexpr int quad_row(int i, int j) {
    return 17 + 16 * i - (i * (i - 1)) / 2 + (j - i);
}

// ---------- helpers ----------
__device__ __forceinline__ uint32_t cvt_bf16x2(float hi, float lo) {
    uint32_t r;
    asm("cvt.rn.bf16x2.f32 %0, %1, %2;" : "=r"(r) : "f"(hi), "f"(lo));
    return r;
}
__device__ __forceinline__ void mma16816(float* d, const uint32_t* a, const uint32_t* b) {
    asm volatile(
        "mma.sync.aligned.m16n8k16.row.col.f32.bf16.bf16.f32 "
        "{%0,%1,%2,%3}, {%4,%5,%6,%7}, {%8,%9}, {%0,%1,%2,%3};"
        : "+f"(d[0]), "+f"(d[1]), "+f"(d[2]), "+f"(d[3])
        : "r"(a[0]), "r"(a[1]), "r"(a[2]), "r"(a[3]), "r"(b[0]), "r"(b[1]));
}
__device__ __forceinline__ void sts64f(uint32_t a, float x, float y) {
    asm volatile("st.shared.v2.f32 [%0], {%1,%2};" :: "r"(a), "f"(x), "f"(y) : "memory");
}
__device__ __forceinline__ void lds128f(uint32_t a, float& x, float& y, float& z, float& w) {
    asm volatile("ld.shared.v4.f32 {%0,%1,%2,%3}, [%4];"
                 : "=f"(x), "=f"(y), "=f"(z), "=f"(w) : "r"(a));
}

// ---------- slot template (validated in R11; indices compile-time) ----------
// s: 0 CONST | 1..4 LIN m=s-1 | 5..8 SQ m=s-5 | 9..36 DPROD d=1+(s-9)/4,m=(s-9)%4
//    | 37..40 D8 m=s-37 | 41..44 SIN m=s-41 | 45..47 ZERO
template <int S>
__device__ __forceinline__ float slot_val(const float* zr) {
    if constexpr (S == 0) return 1.0f;
    else if constexpr (S <= 4) return zr[S - 1];
    else if constexpr (S <= 8) { constexpr int m = S - 5; return zr[m] * zr[m]; }
    else if constexpr (S <= 36) {
        constexpr int d = 1 + (S - 9) / 4, m = (S - 9) % 4;
        return zr[m] * zr[(m + d) & 15];
    }
    else if constexpr (S <= 40) { constexpr int m = S - 37; return zr[m] * zr[m + 8]; }
    else if constexpr (S <= 44) return __sinf(zr[S - 41]);
    else return 0.0f;
}

// real feature for slot s as seen by thread c4 (C permutation; validated R11)
__device__ __forceinline__ int slot_feature(int s, int c4) {
    if (s == 0) return (c4 == 0) ? 0 : -1;
    if (s <= 4)  { int a = (s - 1 + 4 * c4) & 15; return 1 + a; }
    if (s <= 8)  { int a = (s - 5 + 4 * c4) & 15; return quad_row(a, a); }
    if (s <= 36) {
        int d = 1 + (s - 9) / 4, m = (s - 9) % 4;
        int a = (m + 4 * c4) & 15, b = (a + d) & 15;
        int i = a < b ? a : b, j = a < b ? b : a;
        return quad_row(i, j);
    }
    if (s <= 40) { int a = (s - 37 + 4 * c4) & 15; return (a < 8) ? quad_row(a, a + 8) : -1; }
    if (s <= 44) { int a = (s - 41 + 4 * c4) & 15; return 153 + a; }
    return -1;
}

// run the 24 MMAs, building A fragments on the fly (2 chains: nt0/nt1)
template <int K>
__device__ __forceinline__ void do_ksteps(
    const float* za, const float* zb, const uint32_t (&B)[KC][2][2],
    float (&D0)[4], float (&D1)[4])
{
    if constexpr (K < KC) {
        uint32_t a[4];
        a[0] = cvt_bf16x2(slot_val<4*K+1>(za), slot_val<4*K+0>(za));
        a[1] = cvt_bf16x2(slot_val<4*K+1>(zb), slot_val<4*K+0>(zb));
        a[2] = cvt_bf16x2(slot_val<4*K+3>(za), slot_val<4*K+2>(za));
        a[3] = cvt_bf16x2(slot_val<4*K+3>(zb), slot_val<4*K+2>(zb));
        mma16816(D0, a, B[K][0]);
        mma16816(D1, a, B[K][1]);
        do_ksteps<K + 1>(za, zb, B, D0, D1);
    }
}

// ---------- kernel ----------
__global__ __launch_bounds__(BLOCK, 2) void sindy_shred_fd2_kernel(
    const float* __restrict__ h_t,
    const float* __restrict__ coef,
    const float* __restrict__ mask,
    float* __restrict__ out,
    int n, int nrep)
{
    // Permuted masked coefficients, transposed: sCT[d][kr] (bf16)
    __shared__ __align__(16) __nv_bfloat16 sCT[LATENT * CT_STRIDE];
    // per-warp dz tile: 16 rows x 16 words, XOR-block swizzle (1KB/warp)
    __shared__ __align__(16) float sdz[WARPS * SPW * 16];

    const int tid  = threadIdx.x;
    const int lane = tid & 31;
    const int warp = tid >> 5;
    const int c4   = lane & 3;
    const int g    = lane >> 2;
    const int r    = blockIdx.y;

    // ---- init: permuted C^T in smem (verbatim from R11; validated) ----
    {
        const float* cb = coef + (size_t)r * NFEAT * LATENT;
        const float* mb = mask + (size_t)r * NFEAT * LATENT;
        for (int idx = tid; idx < KROWS * LATENT; idx += BLOCK) {
            int kr = idx >> 4, d = idx & 15;
            int c4k = (kr >> 1) & 3;
            int p   = (kr & 1) | (((kr >> 3) & 1) << 1);
            int s   = (kr >> 4) * 4 + p;
            int f   = slot_feature(s, c4k);
            float v = 0.0f;
            if (f >= 0) v = cb[f * LATENT + d] * mb[f * LATENT + d];
            sCT[d * CT_STRIDE + kr] = __float2bfloat16(v);
        }
    }
    __syncthreads();

    // ---- static B fragments (extraction formula validated in R11) ----
    // B[k][nt]: b0 = (k rows 2c4,2c4+1; dim nt*8+g), b1 = rows +8
    uint32_t B[KC][2][2];
    {
        const uint32_t* ctp = reinterpret_cast<const uint32_t*>(sCT);
        #pragma unroll
        for (int k = 0; k < KC; k++) {
            const int ku = 8 * k + c4;
            #pragma unroll
            for (int nt = 0; nt < 2; nt++) {
                const int row = (nt * 8 + g) * (CT_STRIDE / 2);
                B[k][nt][0] = ctp[row + ku];
                B[k][nt][1] = ctp[row + ku + 4];
            }
        }
    }

    // ---- two samples per thread, rotated z: zr[t] = z[(t+4c4)&15] ----
    const int sa = blockIdx.x * SCTA + warp * SPW + g;       // sample row g
    const int sb = sa + 8;                                   // sample row g+8
    const bool va = sa < n, vb = sb < n;

    float za[LATENT], zb[LATENT];
    #pragma unroll
    for (int d = 0; d < LATENT; d++) { za[d] = 0.0f; zb[d] = 0.0f; }
    if (va) {
        const float4* hp = reinterpret_cast<const float4*>(h_t + (size_t)sa * LATENT);
        #pragma unroll
        for (int q = 0; q < 4; q++) {
            float4 v = hp[(q + c4) & 3];
            za[4*q+0] = v.x; za[4*q+1] = v.y; za[4*q+2] = v.z; za[4*q+3] = v.w;
        }
    }
    if (vb) {
        const float4* hp = reinterpret_cast<const float4*>(h_t + (size_t)sb * LATENT);
        #pragma unroll
        for (int q = 0; q < 4; q++) {
            float4 v = hp[(q + c4) & 3];
            zb[4*q+0] = v.x; zb[4*q+1] = v.y; zb[4*q+2] = v.z; zb[4*q+3] = v.w;
        }
    }

    const uint32_t dzw =
        (uint32_t)__cvta_generic_to_shared(sdz + warp * SPW * 16);
    // swizzled word: row*16 + ((blk ^ (row&3))*4 + off)
    const int gs = g & 3;        // swizzle key for rows g and g+8 (same &3)

    #pragma unroll 1
    for (int st = 0; st < NSTEPS; st++) {
        float D0[4] = {0.f, 0.f, 0.f, 0.f};   // dims nt0: 0..7
        float D1[4] = {0.f, 0.f, 0.f, 0.f};   // dims nt1: 8..15
        do_ksteps<0>(za, zb, B, D0, D1);

        // scatter: thread holds dims {2c4,2c4+1} (D*[0],D*[1]) of sample row g
        // and (D*[2],D*[3]) of row g+8, for nt blocks {c4>>1, 2+(c4>>1)}.
        {
            const int b0 = c4 >> 1, off = (2 * c4) & 3;
            const uint32_t ra = (uint32_t)(g * 16);
            const uint32_t rb = (uint32_t)((g + 8) * 16);
            sts64f(dzw + 4u * (ra + (uint32_t)((b0 ^ gs) * 4 + off)),       D0[0], D0[1]);
            sts64f(dzw + 4u * (ra + (uint32_t)(((b0 + 2) ^ gs) * 4 + off)), D1[0], D1[1]);
            sts64f(dzw + 4u * (rb + (uint32_t)((b0 ^ gs) * 4 + off)),       D0[2], D0[3]);
            sts64f(dzw + 4u * (rb + (uint32_t)(((b0 + 2) ^ gs) * 4 + off)), D1[2], D1[3]);
        }
        __syncwarp();

        // gather rotated: zr block q = real block (q+c4)&3, swizzled by row
        #pragma unroll
        for (int q = 0; q < 4; q++) {
            const int rb4 = ((q + c4) & 3) ^ gs;
            float4 dv;
            lds128f(dzw + 4u * (uint32_t)(g * 16 + rb4 * 4), dv.x, dv.y, dv.z, dv.w);
            za[4*q+0] = fmaf(dv.x, DT_F, za[4*q+0]);
            za[4*q+1] = fmaf(dv.y, DT_F, za[4*q+1]);
            za[4*q+2] = fmaf(dv.z, DT_F, za[4*q+2]);
            za[4*q+3] = fmaf(dv.w, DT_F, za[4*q+3]);
            lds128f(dzw + 4u * (uint32_t)((g + 8) * 16 + rb4 * 4), dv.x, dv.y, dv.z, dv.w);
            zb[4*q+0] = fmaf(dv.x, DT_F, zb[4*q+0]);
            zb[4*q+1] = fmaf(dv.y, DT_F, zb[4*q+1]);
            zb[4*q+2] = fmaf(dv.z, DT_F, zb[4*q+2]);
            zb[4*q+3] = fmaf(dv.w, DT_F, zb[4*q+3]);
        }
        __syncwarp();   // reads done before next step's scatter
    }

    // ---- output: zr block 0 = real dim block c4 ----
    if (va) {
        float4 v; v.x = za[0]; v.y = za[1]; v.z = za[2]; v.w = za[3];
        reinterpret_cast<float4*>(out + ((size_t)sa * nrep + r) * LATENT)[c4] = v;
    }
    if (vb) {
        float4 v; v.x = zb[0]; v.y = zb[1]; v.z = zb[2]; v.w = zb[3];
        reinterpret_cast<float4*>(out + ((size_t)sb * nrep + r) * LATENT)[c4] = v;
    }
}

extern "C" void kernel_launch(void* const* d_in, const int* in_sizes, int n_in,
                              void* d_out, int out_size) {
    const float* h_t  = (const float*)d_in[0];
    const float* coef = (const float*)d_in[1];
    const float* mask = (const float*)d_in[2];
    float* out = (float*)d_out;

    int n    = in_sizes[0] / LATENT;            // samples
    int nrep = in_sizes[1] / (NFEAT * LATENT);  // replicates

    dim3 block(BLOCK);
    dim3 grid((n + SCTA - 1) / SCTA, nrep);
    sindy_shred_fd2_kernel<<<grid, block>>>(h_t, coef, mask, out, n, nrep);
}

// round 13
// speedup vs baseline: 1.6373x; 1.1211x over previous
#include <cuda_runtime.h>
#include <cuda_bf16.h>
#include <cstdint>

// SINDy_SHRED, fragment-direct HMMA v3: packed-bf16x2 theta generation.
// dz[16 samples, 16 dims] = Theta[16, 192] @ C_perm[192, 16] per warp-step.
// vs R12 (191us): A-fragments now cost ONE mul.bf16x2 each instead of
// 2 FMUL + 1 CVT, via a re-paired slot template whose (even,odd) pairs are
// componentwise products of packed vectors P[t] = (zr[t], zr[t+1]):
//   squares  = mul(P0,P0), mul(P2,P2)
//   delta d  = mul(P0,P[d]), mul(P2,P[d+2])   (d = 1..7)
//   delta 8  = mul(P0,P8),  mul(P2,P10)
//   linear   = P0, P2 directly; const pair = 0x00003F80; sin = MUFU+cvt.
// slot_feature (C permutation) rewritten to match the new pairing; rotation
// machinery, B extraction, swizzled dz exchange all verbatim from R12
// (validated, rel_err 2.94e-6).

#define LATENT 16
#define NFEAT 169
#define NSTEPS 10
#define DT_F 0.01f
#define KC 12                // k-steps of 16 -> 192 slots
#define KROWS 192
#define WARPS 8
#define BLOCK 256
#define SPW 16               // samples per warp
#define SCTA (WARPS * SPW)   // 128
#define CT_STRIDE 192        // permuted C^T row length in bf16 (per dim)

__host__ __device__ __forceinline__ constexpr int quad_row(int i, int j) {
    return 17 + 16 * i - (i * (i - 1)) / 2 + (j - i);
}

// ---------- helpers ----------
__device__ __forceinline__ uint32_t cvt_bf16x2(float hi, float lo) {
    uint32_t r;
    asm("cvt.rn.bf16x2.f32 %0, %1, %2;" : "=r"(r) : "f"(hi), "f"(lo));
    return r;
}
__device__ __forceinline__ uint32_t mul_bf16x2(uint32_t a, uint32_t b) {
    uint32_t r;
    asm("mul.bf16x2 %0, %1, %2;" : "=r"(r) : "r"(a), "r"(b));
    return r;
}
__device__ __forceinline__ void mma16816(float* d, const uint32_t* a, const uint32_t* b) {
    asm volatile(
        "mma.sync.aligned.m16n8k16.row.col.f32.bf16.bf16.f32 "
        "{%0,%1,%2,%3}, {%4,%5,%6,%7}, {%8,%9}, {%0,%1,%2,%3};"
        : "+f"(d[0]), "+f"(d[1]), "+f"(d[2]), "+f"(d[3])
        : "r"(a[0]), "r"(a[1]), "r"(a[2]), "r"(a[3]), "r"(b[0]), "r"(b[1]));
}
__device__ __forceinline__ void sts64f(uint32_t a, float x, float y) {
    asm volatile("st.shared.v2.f32 [%0], {%1,%2};" :: "r"(a), "f"(x), "f"(y) : "memory");
}
__device__ __forceinline__ void lds128f(uint32_t a, float& x, float& y, float& z, float& w) {
    asm volatile("ld.shared.v4.f32 {%0,%1,%2,%3}, [%4];"
                 : "=f"(x), "=f"(y), "=f"(z), "=f"(w) : "r"(a));
}

// ---------- pair template (pair p covers slots 2p, 2p+1) ----------
// p0: (1, 0) const | p1: (z0,z1)=P0 | p2: (z2,z3)=P2
// p3: P0*P0 | p4: P2*P2
// p 5..18: d=1..7 -> odd p=3+2d: P0*P[d]; even p=4+2d: P2*P[d+2]
// p19: P0*P8 | p20: P2*P10 | p21: (sin z0, sin z1) | p22: (sin z2, sin z3)
// p23: (0, 0)
template <int P>
__device__ __forceinline__ uint32_t pair_val(const uint32_t* Pk, const float* zr) {
    if constexpr (P == 0) return 0x00003F80u;           // (lo=1.0bf, hi=0)
    else if constexpr (P == 1) return Pk[0];
    else if constexpr (P == 2) return Pk[2];
    else if constexpr (P == 3) return mul_bf16x2(Pk[0], Pk[0]);
    else if constexpr (P == 4) return mul_bf16x2(Pk[2], Pk[2]);
    else if constexpr (P >= 5 && P <= 18) {
        if constexpr (P & 1) { constexpr int d = (P - 3) / 2; return mul_bf16x2(Pk[0], Pk[d]); }
        else                 { constexpr int d = (P - 4) / 2; return mul_bf16x2(Pk[2], Pk[d + 2]); }
    }
    else if constexpr (P == 19) return mul_bf16x2(Pk[0], Pk[8]);
    else if constexpr (P == 20) return mul_bf16x2(Pk[2], Pk[10]);
    else if constexpr (P == 21) return cvt_bf16x2(__sinf(zr[1]), __sinf(zr[0]));
    else if constexpr (P == 22) return cvt_bf16x2(__sinf(zr[3]), __sinf(zr[2]));
    else return 0u;
}

// real feature for slot s of thread c4 (matches the pairing above)
__device__ __forceinline__ int slot_feature(int s, int c4) {
    const int rot = 4 * c4;
    if (s == 0) return (c4 == 0) ? 0 : -1;      // const (one real copy)
    if (s == 1) return -1;                      // pad
    if (s <= 5)  { int a = (s - 2 + rot) & 15; return 1 + a; }            // linear
    if (s <= 9)  { int a = (s - 6 + rot) & 15; return quad_row(a, a); }   // squares
    if (s <= 37) {                                                        // delta 1..7
        int idx = s - 10, d = 1 + idx / 4, m = idx & 3;
        int a = (m + rot) & 15, b = (a + d) & 15;
        int i = a < b ? a : b, j = a < b ? b : a;
        return quad_row(i, j);
    }
    if (s <= 41) {                                                        // delta 8
        int m = s - 38; int a = (m + rot) & 15;
        return (a < 8) ? quad_row(a, a + 8) : -1;
    }
    if (s <= 45) { int a = (s - 42 + rot) & 15; return 153 + a; }         // sin
    return -1;                                                            // pad
}

// 24 MMAs; a-regs built on the fly from packed P vectors
template <int K>
__device__ __forceinline__ void do_ksteps(
    const uint32_t* PA, const uint32_t* PB, const float* za, const float* zb,
    const uint32_t (&B)[KC][2][2], float (&D0)[4], float (&D1)[4])
{
    if constexpr (K < KC) {
        uint32_t a[4];
        a[0] = pair_val<2 * K>(PA, za);
        a[1] = pair_val<2 * K>(PB, zb);
        a[2] = pair_val<2 * K + 1>(PA, za);
        a[3] = pair_val<2 * K + 1>(PB, zb);
        mma16816(D0, a, B[K][0]);
        mma16816(D1, a, B[K][1]);
        do_ksteps<K + 1>(PA, PB, za, zb, B, D0, D1);
    }
}

// ---------- kernel ----------
__global__ __launch_bounds__(BLOCK, 2) void sindy_shred_fd3_kernel(
    const float* __restrict__ h_t,
    const float* __restrict__ coef,
    const float* __restrict__ mask,
    float* __restrict__ out,
    int n, int nrep)
{
    __shared__ __align__(16) __nv_bfloat16 sCT[LATENT * CT_STRIDE];
    __shared__ __align__(16) float sdz[WARPS * SPW * 16];

    const int tid  = threadIdx.x;
    const int lane = tid & 31;
    const int warp = tid >> 5;
    const int c4   = lane & 3;
    const int g    = lane >> 2;
    const int r    = blockIdx.y;

    // ---- init: permuted C^T in smem ----
    {
        const float* cb = coef + (size_t)r * NFEAT * LATENT;
        const float* mb = mask + (size_t)r * NFEAT * LATENT;
        for (int idx = tid; idx < KROWS * LATENT; idx += BLOCK) {
            int kr = idx >> 4, d = idx & 15;
            int c4k = (kr >> 1) & 3;
            int p   = (kr & 1) | (((kr >> 3) & 1) << 1);
            int s   = (kr >> 4) * 4 + p;
            int f   = slot_feature(s, c4k);
            float v = 0.0f;
            if (f >= 0) v = cb[f * LATENT + d] * mb[f * LATENT + d];
            sCT[d * CT_STRIDE + kr] = __float2bfloat16(v);
        }
    }
    __syncthreads();

    // ---- static B fragments (validated extraction) ----
    uint32_t B[KC][2][2];
    {
        const uint32_t* ctp = reinterpret_cast<const uint32_t*>(sCT);
        #pragma unroll
        for (int k = 0; k < KC; k++) {
            const int ku = 8 * k + c4;
            #pragma unroll
            for (int nt = 0; nt < 2; nt++) {
                const int row = (nt * 8 + g) * (CT_STRIDE / 2);
                B[k][nt][0] = ctp[row + ku];
                B[k][nt][1] = ctp[row + ku + 4];
            }
        }
    }

    // ---- two samples per thread, rotated z ----
    const int sa = blockIdx.x * SCTA + warp * SPW + g;
    const int sb = sa + 8;
    const bool va = sa < n, vb = sb < n;

    float za[LATENT], zb[LATENT];
    #pragma unroll
    for (int d = 0; d < LATENT; d++) { za[d] = 0.0f; zb[d] = 0.0f; }
    if (va) {
        const float4* hp = reinterpret_cast<const float4*>(h_t + (size_t)sa * LATENT);
        #pragma unroll
        for (int q = 0; q < 4; q++) {
            float4 v = hp[(q + c4) & 3];
            za[4*q+0] = v.x; za[4*q+1] = v.y; za[4*q+2] = v.z; za[4*q+3] = v.w;
        }
    }
    if (vb) {
        const float4* hp = reinterpret_cast<const float4*>(h_t + (size_t)sb * LATENT);
        #pragma unroll
        for (int q = 0; q < 4; q++) {
            float4 v = hp[(q + c4) & 3];
            zb[4*q+0] = v.x; zb[4*q+1] = v.y; zb[4*q+2] = v.z; zb[4*q+3] = v.w;
        }
    }

    const uint32_t dzw =
        (uint32_t)__cvta_generic_to_shared(sdz + warp * SPW * 16);
    const int gs = g & 3;

    #pragma unroll 1
    for (int st = 0; st < NSTEPS; st++) {
        // packed vectors P[t] = (lo=zr[t], hi=zr[t+1]), t = 0..10
        uint32_t PA[11], PB[11];
        #pragma unroll
        for (int t = 0; t < 11; t++) {
            PA[t] = cvt_bf16x2(za[t + 1], za[t]);
            PB[t] = cvt_bf16x2(zb[t + 1], zb[t]);
        }

        float D0[4] = {0.f, 0.f, 0.f, 0.f};
        float D1[4] = {0.f, 0.f, 0.f, 0.f};
        do_ksteps<0>(PA, PB, za, zb, B, D0, D1);

        // scatter (verbatim R12, swizzled, conflict-free)
        {
            const int b0 = c4 >> 1, off = (2 * c4) & 3;
            const uint32_t ra = (uint32_t)(g * 16);
            const uint32_t rb = (uint32_t)((g + 8) * 16);
            sts64f(dzw + 4u * (ra + (uint32_t)((b0 ^ gs) * 4 + off)),       D0[0], D0[1]);
            sts64f(dzw + 4u * (ra + (uint32_t)(((b0 + 2) ^ gs) * 4 + off)), D1[0], D1[1]);
            sts64f(dzw + 4u * (rb + (uint32_t)((b0 ^ gs) * 4 + off)),       D0[2], D0[3]);
            sts64f(dzw + 4u * (rb + (uint32_t)(((b0 + 2) ^ gs) * 4 + off)), D1[2], D1[3]);
        }
        __syncwarp();

        // gather rotated (verbatim R12)
        #pragma unroll
        for (int q = 0; q < 4; q++) {
            const int rb4 = ((q + c4) & 3) ^ gs;
            float4 dv;
            lds128f(dzw + 4u * (uint32_t)(g * 16 + rb4 * 4), dv.x, dv.y, dv.z, dv.w);
            za[4*q+0] = fmaf(dv.x, DT_F, za[4*q+0]);
            za[4*q+1] = fmaf(dv.y, DT_F, za[4*q+1]);
            za[4*q+2] = fmaf(dv.z, DT_F, za[4*q+2]);
            za[4*q+3] = fmaf(dv.w, DT_F, za[4*q+3]);
            lds128f(dzw + 4u * (uint32_t)((g + 8) * 16 + rb4 * 4), dv.x, dv.y, dv.z, dv.w);
            zb[4*q+0] = fmaf(dv.x, DT_F, zb[4*q+0]);
            zb[4*q+1] = fmaf(dv.y, DT_F, zb[4*q+1]);
            zb[4*q+2] = fmaf(dv.z, DT_F, zb[4*q+2]);
            zb[4*q+3] = fmaf(dv.w, DT_F, zb[4*q+3]);
        }
        __syncwarp();
    }

    // ---- output: zr block 0 = real dim block c4 ----
    if (va) {
        float4 v; v.x = za[0]; v.y = za[1]; v.z = za[2]; v.w = za[3];
        reinterpret_cast<float4*>(out + ((size_t)sa * nrep + r) * LATENT)[c4] = v;
    }
    if (vb) {
        float4 v; v.x = zb[0]; v.y = zb[1]; v.z = zb[2]; v.w = zb[3];
        reinterpret_cast<float4*>(out + ((size_t)sb * nrep + r) * LATENT)[c4] = v;
    }
}

extern "C" void kernel_launch(void* const* d_in, const int* in_sizes, int n_in,
                              void* d_out, int out_size) {
    const float* h_t  = (const float*)d_in[0];
    const float* coef = (const float*)d_in[1];
    const float* mask = (const float*)d_in[2];
    float* out = (float*)d_out;

    int n    = in_sizes[0] / LATENT;            // samples
    int nrep = in_sizes[1] / (NFEAT * LATENT);  // replicates

    dim3 block(BLOCK);
    dim3 grid((n + SCTA - 1) / SCTA, nrep);
    sindy_shred_fd3_kernel<<<grid, block>>>(h_t, coef, mask, out, n, nrep);
}